// round 12
// baseline (speedup 1.0000x reference)
#include <cuda_runtime.h>
#include <stdint.h>

#define IN_DIM 16384
#define HID    128
#define ALLN   200000
#define NODES  2000
#define SEG    100
#define NSAMP  128

// Output layout (float32):
//   [0, 256000)            positions[s][n]  (s-major)
//   [256000, 256128)       log_softmax[s]
//   [256128, 456128)       scores[0..200000)
#define OFF_LOGSM (NSAMP * NODES)
#define OFF_SCORES (NSAMP * NODES + NSAMP)

#define NPART 512

// ---------------- device scratch (no allocation allowed) ----------------
__device__ float g_hpart[NPART][HID];
__device__ float g_hs[HID];
__device__ unsigned g_arrive;   // zero-initialized; self-resetting each launch

// ---------------- XLA f32 tanh (Eigen-style rational approx) ----------------
__device__ __forceinline__ float tanh_xla(float x) {
    float ax = fabsf(x);
    if (ax < 0.0004f) return x;
    float xc = fminf(fmaxf(x, -9.0f), 9.0f);
    float x2 = xc * xc;
    float np = fmaf(x2, -2.76076847742355e-16f, 2.00018790482477e-13f);
    np = fmaf(x2, np, -8.60467152213735e-11f);
    np = fmaf(x2, np, 5.12229709037114e-08f);
    np = fmaf(x2, np, 1.48572235717979e-05f);
    np = fmaf(x2, np, 6.37261928875436e-04f);
    np = fmaf(x2, np, 4.89352455891786e-03f);
    np = np * xc;
    float dp = fmaf(x2, 1.19825839466702e-06f, 1.18534705686654e-04f);
    dp = fmaf(x2, dp, 2.26843463243900e-03f);
    dp = fmaf(x2, dp, 4.89352518554385e-03f);
    return np / dp;
}

// ---------------- threefry2x32, key=(0,42), counts=(0, i) --------------------
// Partitionable JAX scheme, 32-bit: bits[i] = out0 ^ out1.
__device__ __forceinline__ unsigned tf_xor(unsigned ctr) {
    const unsigned K0 = 0u;
    const unsigned K1 = 42u;
    const unsigned K2 = 0u ^ 42u ^ 0x1BD11BDAu;
    unsigned a = ctr + K1;
    unsigned x0 = a;                                  // round 1 (x0 was 0)
    unsigned x1 = __funnelshift_l(a, a, 13) ^ a;
#define TFR(r) { x0 += x1; x1 = __funnelshift_l(x1, x1, (r)); x1 ^= x0; }
    TFR(15) TFR(26) TFR(6)
    x0 += K1; x1 += K2 + 1u;
    TFR(17) TFR(29) TFR(16) TFR(24)
    x0 += K2; x1 += K0 + 2u;
    TFR(13) TFR(15) TFR(26) TFR(6)
    x0 += K0; x1 += K1 + 3u;
    TFR(17) TFR(29) TFR(16) TFR(24)
    x0 += K1; x1 += K2 + 4u;
    TFR(13) TFR(15) TFR(26) TFR(6)
    x0 += K2; x1 += K0 + 5u;
#undef TFR
    return x0 ^ x1;
}

// Exact JAX gumbel+score value (precise libdevice logf) — final arbiter only.
__device__ __forceinline__ float precise_v(unsigned ctr, float rowk) {
    unsigned b = tf_xor(ctr);
    float f = __uint_as_float((b >> 9) | 0x3f800000u) - 1.0f;
    float u = fmaxf(f, 1.17549435e-38f);
    return -logf(-logf(u)) + rowk;
}

// ---------------- K1: partials of x @ W1; last block reduces -> hs -----------
// 512 blocks x 256 threads; block b covers input rows [b*32, b*32+32).
__global__ void k_h(const float* __restrict__ x, const float* __restrict__ W1,
                    const float* __restrict__ b1, float* __restrict__ out) {
    __shared__ float4 sm[8][32];
    __shared__ int is_last;
    int t = threadIdx.x;
    int lane = t & 31;
    int grp = t >> 5;
    int i0 = blockIdx.x * 32 + grp * 4;
    float4 acc = make_float4(0.f, 0.f, 0.f, 0.f);
#pragma unroll
    for (int ii = 0; ii < 4; ii++) {
        int i = i0 + ii;
        float xi = x[i];
        float4 w = *(const float4*)(W1 + i * HID + lane * 4);
        acc.x = fmaf(xi, w.x, acc.x);
        acc.y = fmaf(xi, w.y, acc.y);
        acc.z = fmaf(xi, w.z, acc.z);
        acc.w = fmaf(xi, w.w, acc.w);
    }
    sm[grp][lane] = acc;
    __syncthreads();
    if (t < 32) {
        float4 s = sm[0][t];
#pragma unroll
        for (int g2 = 1; g2 < 8; g2++) {
            float4 o = sm[g2][t];
            s.x += o.x; s.y += o.y; s.z += o.z; s.w += o.w;
        }
        *(float4*)(&g_hpart[blockIdx.x][t * 4]) = s;
    }
    // arrival protocol: last block fuses the reduction
    __threadfence();
    __syncthreads();
    if (t == 0) {
        unsigned prev = atomicAdd(&g_arrive, 1u);
        is_last = (prev == NPART - 1u) ? 1 : 0;
    }
    __syncthreads();
    if (!is_last) return;
    __threadfence();  // acquire: all partials visible

    int j = t & 127;
    int q = t >> 7;
    float s = 0.0f;
#pragma unroll 8
    for (int b = 0; b < NPART / 2; b++) s += g_hpart[q * (NPART / 2) + b][j];
    ((float*)sm)[t] = s;
    __syncthreads();
    if (t < 128) {
        float tot = b1[j] + (((float*)sm)[j] + ((float*)sm)[j + 128]);
        g_hs[j] = tanh_xla(tot);
        out[OFF_LOGSM + j] = 0.0f;
    }
    if (t == 0) g_arrive = 0u;  // self-reset for next (graph) launch
}

// ---------------- K2 fused: scores + rowstats + gumbel sampling --------------
// block = node n (2000 blocks x 128 threads); thread t = sample s.
__global__ void __launch_bounds__(128) k_fused(const float* __restrict__ W2,
                                               const float* __restrict__ b2,
                                               float* __restrict__ out) {
    __shared__ float hs[HID];
    __shared__ float srow[SEG];
    __shared__ float negsexp[SEG];   // -exp(-srow[k]) for one-MUFU ranking
    __shared__ float red[8];
    __shared__ float sstat[2];       // rowmax, log(sumexp)
    const int n = blockIdx.x;
    const int t = threadIdx.x;
    const float NEGINF = -__int_as_float(0x7f800000);
    const float POSINF =  __int_as_float(0x7f800000);

    hs[t] = g_hs[t];
    __syncthreads();

    // --- scores for this node's 100 columns (coalesced over t) ---
    if (t < SEG) {
        int col = n * SEG + t;
        float acc = b2[col];
#pragma unroll 8
        for (int k = 0; k < HID; k++)
            acc = fmaf(hs[k], W2[(size_t)k * ALLN + col], acc);
        float sc = 10.0f * tanh_xla(acc);
        srow[t] = sc;
        negsexp[t] = -expf(-sc);
        out[OFF_SCORES + col] = sc;
    }
    __syncthreads();

    // --- rowmax ---
    float v = (t < SEG) ? srow[t] : NEGINF;
#pragma unroll
    for (int off = 16; off > 0; off >>= 1)
        v = fmaxf(v, __shfl_xor_sync(0xffffffffu, v, off));
    if ((t & 31) == 0) red[t >> 5] = v;
    __syncthreads();
    if (t == 0) sstat[0] = fmaxf(fmaxf(red[0], red[1]), fmaxf(red[2], red[3]));
    __syncthreads();

    // --- log(sum(exp(x - max))) ---
    float e = (t < SEG) ? expf(srow[t] - sstat[0]) : 0.0f;
#pragma unroll
    for (int off = 16; off > 0; off >>= 1)
        e += __shfl_xor_sync(0xffffffffu, e, off);
    if ((t & 31) == 0) red[4 + (t >> 5)] = e;
    __syncthreads();
    if (t == 0) sstat[1] = logf((red[4] + red[5]) + (red[6] + red[7]));
    __syncthreads();

    // --- sampling: thread t = sample s ---
    // argmax_k (g_k + srow_k) == argmin_k m_k with
    //   m_k = lg2(u_k) * (-exp(-srow_k))   (> 0; one MUFU per gumbel)
    // No fmax in fast path: b>>9 == 0 gives m = +inf (self-excluding; the true
    // value for that draw, -log(87.3)+score, can never win a 100-way argmax).
    // Track top-2 (predicated — keeps off the saturated alu pipe), then
    // arbitrate with the exact JAX expression.
    unsigned base = (unsigned)t * (unsigned)(NODES * SEG) + (unsigned)n * (unsigned)SEG;
    float m1 = POSINF, m2 = POSINF;
    int bk = 0, k2 = 0;
#pragma unroll 10
    for (int k = 0; k < SEG; k++) {
        unsigned b = tf_xor(base + (unsigned)k);
        float u = __uint_as_float((b >> 9) | 0x3f800000u) - 1.0f;
        float m = __log2f(u) * negsexp[k];     // lg2(u) <= 0, negsexp < 0 -> m >= 0
        if (m < m1) { m2 = m1; k2 = bk; m1 = m; bk = k; }
        else if (m < m2) { m2 = m; k2 = k; }
    }
    // precise arbitration between the two fast candidates (tie -> smaller k)
    float p1 = precise_v(base + (unsigned)bk, srow[bk]);
    float p2 = precise_v(base + (unsigned)k2, srow[k2]);
    if (p2 > p1 || (p2 == p1 && k2 < bk)) bk = k2;

    out[t * NODES + n] = (float)bk;
    float lp = (srow[bk] - sstat[0]) - sstat[1];
    atomicAdd(&out[OFF_LOGSM + t], lp);
}

// ---------------- launch ----------------
extern "C" void kernel_launch(void* const* d_in, const int* in_sizes, int n_in,
                              void* d_out, int out_size) {
    const float* x  = (const float*)d_in[0];
    const float* W1 = (const float*)d_in[1];
    const float* b1 = (const float*)d_in[2];
    const float* W2 = (const float*)d_in[3];
    const float* b2 = (const float*)d_in[4];
    float* out = (float*)d_out;

    k_h<<<NPART, 256>>>(x, W1, b1, out);
    k_fused<<<NODES, 128>>>(W2, b2, out);
}

// round 13
// speedup vs baseline: 1.0925x; 1.0925x over previous
#include <cuda_runtime.h>
#include <stdint.h>

#define IN_DIM 16384
#define HID    128
#define ALLN   200000
#define NODES  2000
#define SEG    100
#define NSAMP  128

// Output layout (float32):
//   [0, 256000)            positions[s][n]  (s-major)
//   [256000, 256128)       log_softmax[s]
//   [256128, 456128)       scores[0..200000)
#define OFF_LOGSM (NSAMP * NODES)
#define OFF_SCORES (NSAMP * NODES + NSAMP)

#define NPART 512

// ---------------- device scratch (no allocation allowed) ----------------
__device__ float g_hpart[NPART][HID];
__device__ float g_hs[HID];

// ---------------- XLA f32 tanh (Eigen-style rational approx) ----------------
__device__ __forceinline__ float tanh_xla(float x) {
    float ax = fabsf(x);
    if (ax < 0.0004f) return x;
    float xc = fminf(fmaxf(x, -9.0f), 9.0f);
    float x2 = xc * xc;
    float np = fmaf(x2, -2.76076847742355e-16f, 2.00018790482477e-13f);
    np = fmaf(x2, np, -8.60467152213735e-11f);
    np = fmaf(x2, np, 5.12229709037114e-08f);
    np = fmaf(x2, np, 1.48572235717979e-05f);
    np = fmaf(x2, np, 6.37261928875436e-04f);
    np = fmaf(x2, np, 4.89352455891786e-03f);
    np = np * xc;
    float dp = fmaf(x2, 1.19825839466702e-06f, 1.18534705686654e-04f);
    dp = fmaf(x2, dp, 2.26843463243900e-03f);
    dp = fmaf(x2, dp, 4.89352518554385e-03f);
    return np / dp;
}

// ---------------- threefry2x32, key=(0,42), counts=(0, i) --------------------
// Partitionable JAX scheme, 32-bit: bits[i] = out0 ^ out1.
__device__ __forceinline__ unsigned tf_xor(unsigned ctr) {
    const unsigned K0 = 0u;
    const unsigned K1 = 42u;
    const unsigned K2 = 0u ^ 42u ^ 0x1BD11BDAu;
    unsigned a = ctr + K1;
    unsigned x0 = a;                                  // round 1 (x0 was 0)
    unsigned x1 = __funnelshift_l(a, a, 13) ^ a;
#define TFR(r) { x0 += x1; x1 = __funnelshift_l(x1, x1, (r)); x1 ^= x0; }
    TFR(15) TFR(26) TFR(6)
    x0 += K1; x1 += K2 + 1u;
    TFR(17) TFR(29) TFR(16) TFR(24)
    x0 += K2; x1 += K0 + 2u;
    TFR(13) TFR(15) TFR(26) TFR(6)
    x0 += K0; x1 += K1 + 3u;
    TFR(17) TFR(29) TFR(16) TFR(24)
    x0 += K1; x1 += K2 + 4u;
    TFR(13) TFR(15) TFR(26) TFR(6)
    x0 += K2; x1 += K0 + 5u;
#undef TFR
    return x0 ^ x1;
}

// Exact JAX gumbel+score value (precise libdevice logf) — final arbiter only.
__device__ __forceinline__ float precise_v(unsigned ctr, float rowk) {
    unsigned b = tf_xor(ctr);
    float f = __uint_as_float((b >> 9) | 0x3f800000u) - 1.0f;
    float u = fmaxf(f, 1.17549435e-38f);
    return -logf(-logf(u)) + rowk;
}

// ---------------- K1: float4 partials of x @ W1 (R10 version) ----------------
__global__ void k_h_partial(const float* __restrict__ x, const float* __restrict__ W1) {
    __shared__ float4 sm[8][32];
    int t = threadIdx.x;
    int lane = t & 31;
    int grp = t >> 5;
    int i0 = blockIdx.x * 32 + grp * 4;
    float4 acc = make_float4(0.f, 0.f, 0.f, 0.f);
#pragma unroll
    for (int ii = 0; ii < 4; ii++) {
        int i = i0 + ii;
        float xi = x[i];
        float4 w = *(const float4*)(W1 + i * HID + lane * 4);
        acc.x = fmaf(xi, w.x, acc.x);
        acc.y = fmaf(xi, w.y, acc.y);
        acc.z = fmaf(xi, w.z, acc.z);
        acc.w = fmaf(xi, w.w, acc.w);
    }
    sm[grp][lane] = acc;
    __syncthreads();
    if (t < 32) {
        float4 s = sm[0][t];
#pragma unroll
        for (int g2 = 1; g2 < 8; g2++) {
            float4 o = sm[g2][t];
            s.x += o.x; s.y += o.y; s.z += o.z; s.w += o.w;
        }
        *(float4*)(&g_hpart[blockIdx.x][t * 4]) = s;
    }
}

// ---------------- K2: reduce partials -> hs; zero log_softmax ----------------
__global__ void k_hsum(const float* __restrict__ b1, float* __restrict__ out) {
    __shared__ float sm[512];
    int t = threadIdx.x;
    int j = t & 127;
    int q = t >> 7;
    float s = 0.0f;
#pragma unroll 8
    for (int b = 0; b < NPART / 4; b++) s += g_hpart[q * (NPART / 4) + b][j];
    sm[t] = s;
    __syncthreads();
    if (t < 128) {
        float tot = b1[j] + ((sm[j] + sm[j + 128]) + (sm[j + 256] + sm[j + 384]));
        g_hs[j] = tanh_xla(tot);
        out[OFF_LOGSM + j] = 0.0f;
    }
}

// ---------------- K3 fused: 256 threads/node; split-k scores, split-row sampling
// t<128: sample t, gumbels [0,50); t>=128: sample t-128, gumbels [50,100).
__global__ void __launch_bounds__(256, 8) k_fused(const float* __restrict__ W2,
                                                  const float* __restrict__ b2,
                                                  float* __restrict__ out) {
    __shared__ float hs[HID];
    __shared__ float srow[SEG];
    __shared__ float negsexp[SEG];
    __shared__ float spart[SEG];     // high-half dot partials
    __shared__ float red[16];
    __shared__ float sstat[2];       // rowmax, log(sumexp)
    __shared__ float cm1[128], cm2[128];
    __shared__ int   ck1[128], ck2[128];
    const int n = blockIdx.x;
    const int t = threadIdx.x;
    const float NEGINF = -__int_as_float(0x7f800000);
    const float POSINF =  __int_as_float(0x7f800000);

    if (t < 128) hs[t] = g_hs[t];
    __syncthreads();

    // --- split-k score phase: t>=128 does HID [64,128), t<100 does [0,64) ---
    if (t >= 128 && t < 128 + SEG) {
        int col = n * SEG + (t - 128);
        float acc = 0.0f;
#pragma unroll 8
        for (int k = 64; k < HID; k++)
            acc = fmaf(hs[k], W2[(size_t)k * ALLN + col], acc);
        spart[t - 128] = acc;
    }
    float acc_lo = 0.0f;
    if (t < SEG) {
        int col = n * SEG + t;
        acc_lo = b2[col];
#pragma unroll 8
        for (int k = 0; k < 64; k++)
            acc_lo = fmaf(hs[k], W2[(size_t)k * ALLN + col], acc_lo);
    }
    __syncthreads();
    if (t < SEG) {
        float sc = 10.0f * tanh_xla(acc_lo + spart[t]);
        srow[t] = sc;
        negsexp[t] = -expf(-sc);
        out[OFF_SCORES + n * SEG + t] = sc;
    }
    __syncthreads();

    // --- rowmax (warps 0-3 carry the data) ---
    float v = (t < SEG) ? srow[t] : NEGINF;
#pragma unroll
    for (int off = 16; off > 0; off >>= 1)
        v = fmaxf(v, __shfl_xor_sync(0xffffffffu, v, off));
    if (t < 128 && (t & 31) == 0) red[t >> 5] = v;
    __syncthreads();
    if (t == 0) sstat[0] = fmaxf(fmaxf(red[0], red[1]), fmaxf(red[2], red[3]));
    __syncthreads();

    // --- log(sum(exp(x - max))) ---
    float e = (t < SEG) ? expf(srow[t] - sstat[0]) : 0.0f;
#pragma unroll
    for (int off = 16; off > 0; off >>= 1)
        e += __shfl_xor_sync(0xffffffffu, e, off);
    if (t < 128 && (t & 31) == 0) red[8 + (t >> 5)] = e;
    __syncthreads();
    if (t == 0) sstat[1] = logf((red[8] + red[9]) + (red[10] + red[11]));
    __syncthreads();

    // --- sampling: 50 gumbels per thread ---
    // argmax_k (g_k + srow_k) == argmin_k m_k, m_k = lg2(u_k) * (-exp(-srow_k)).
    // b>>9 == 0 gives m = +inf (self-excluding; true value can never win).
    const int s = t & 127;
    const int half = t >> 7;
    const int k0 = half * (SEG / 2);
    unsigned base = (unsigned)s * (unsigned)(NODES * SEG) + (unsigned)n * (unsigned)SEG;
    float m1 = POSINF, m2 = POSINF;
    int i1 = k0, i2 = k0;
#pragma unroll 10
    for (int kk = 0; kk < SEG / 2; kk++) {
        int k = k0 + kk;
        unsigned b = tf_xor(base + (unsigned)k);
        float u = __uint_as_float((b >> 9) | 0x3f800000u) - 1.0f;
        float m = __log2f(u) * negsexp[k];
        if (m < m1) { m2 = m1; i2 = i1; m1 = m; i1 = k; }
        else if (m < m2) { m2 = m; i2 = k; }
    }
    if (half) { cm1[s] = m1; cm2[s] = m2; ck1[s] = i1; ck2[s] = i2; }
    __syncthreads();
    if (t < 128) {
        // merge own (low-half) top-2 with pair's (high-half) top-2
        float b1m = cm1[s], b2m = cm2[s];
        int   b1k = ck1[s], b2k = ck2[s];
        float f1, f2; int j1, j2;
        if (m1 <= b1m) {
            f1 = m1; j1 = i1;
            if (m2 <= b1m) { f2 = m2; j2 = i2; } else { f2 = b1m; j2 = b1k; }
        } else {
            f1 = b1m; j1 = b1k;
            if (b2m <= m1) { f2 = b2m; j2 = b2k; } else { f2 = m1; j2 = i1; }
        }
        (void)f1; (void)f2;
        // precise arbitration between the merged top-2 (tie -> smaller k)
        float p1 = precise_v(base + (unsigned)j1, srow[j1]);
        float p2 = precise_v(base + (unsigned)j2, srow[j2]);
        int bk = (p2 > p1 || (p2 == p1 && j2 < j1)) ? j2 : j1;

        out[s * NODES + n] = (float)bk;
        float lp = (srow[bk] - sstat[0]) - sstat[1];
        atomicAdd(&out[OFF_LOGSM + s], lp);
    }
}

// ---------------- launch ----------------
extern "C" void kernel_launch(void* const* d_in, const int* in_sizes, int n_in,
                              void* d_out, int out_size) {
    const float* x  = (const float*)d_in[0];
    const float* W1 = (const float*)d_in[1];
    const float* b1 = (const float*)d_in[2];
    const float* W2 = (const float*)d_in[3];
    const float* b2 = (const float*)d_in[4];
    float* out = (float*)d_out;

    k_h_partial<<<NPART, 256>>>(x, W1);
    k_hsum<<<1, 512>>>(b1, out);
    k_fused<<<NODES, 256>>>(W2, b2, out);
}